// round 2
// baseline (speedup 1.0000x reference)
#include <cuda_runtime.h>
#include <cuda_fp16.h>

// SimpleGraphHead fused kernel.
// B=128 batches, N=64 objects, cl=64, 2cl=128.
// One CTA per batch. Pairwise relational MLP done with mma.sync.m16n8k16
// (fp16 inputs, fp32 accumulate), activations kept in registers between layers.

#define NWARPS 8
#define NTHREADS 256

struct Smem {
    float H[64][64];        // state-encoder output h[b]  (16 KB)
    float P1[64][128];      // h@rc_w1[:64] + rc_b1       (32 KB)
    float P2[64][132];      // h@rc_w1[64:128]  (padded)  (33 KB)
    float Q1[64][64];       // h@an_w1[:64] + an_b1       (16 KB)
    float Q2[64][68];       // h@an_w1[64:128]  (padded)  (17 KB)
    __half W2T[128][136];   // rc_w2 transposed, padded   (34 KB)
    __half W3T[128][136];   // rc_w3 transposed, padded   (34 KB)
    __half AW2T[128][72];   // an_w2 transposed, padded   (18 KB)
    float w1L[128];         // rc_w1[128,:]  (dist row)
    float aw1L[64];         // an_w1[128,:]
    float b2s[128], b3s[128], ab2s[128];
    float hx[64], hy[64];
    float accs[128];        // sum over all pairs of rel*att
    float msum[128];        // sum_i relu(h_i@sd_w1 + sd_b1)
};

__device__ __forceinline__ unsigned pack2(float x, float y) {
    __half2 h = __floats2half2_rn(x, y);
    return *reinterpret_cast<unsigned*>(&h);
}

__device__ __forceinline__ void mma16816(float* d, const unsigned* a,
                                         unsigned b0, unsigned b1) {
    asm volatile(
        "mma.sync.aligned.m16n8k16.row.col.f32.f16.f16.f32 "
        "{%0,%1,%2,%3}, {%4,%5,%6,%7}, {%8,%9}, {%0,%1,%2,%3};\n"
        : "+f"(d[0]), "+f"(d[1]), "+f"(d[2]), "+f"(d[3])
        : "r"(a[0]), "r"(a[1]), "r"(a[2]), "r"(a[3]), "r"(b0), "r"(b1));
}

__global__ void __launch_bounds__(NTHREADS, 1)
sgh_kernel(const float* __restrict__ s,
           const float* __restrict__ se_w1, const float* __restrict__ se_b1,
           const float* __restrict__ se_w2, const float* __restrict__ se_b2,
           const float* __restrict__ sd_w1, const float* __restrict__ sd_b1,
           const float* __restrict__ sd_w2, const float* __restrict__ sd_b2,
           const float* __restrict__ rc_w1, const float* __restrict__ rc_b1,
           const float* __restrict__ rc_w2, const float* __restrict__ rc_b2,
           const float* __restrict__ rc_w3, const float* __restrict__ rc_b3,
           const float* __restrict__ an_w1, const float* __restrict__ an_b1,
           const float* __restrict__ an_w2, const float* __restrict__ an_b2,
           float* __restrict__ out) {
    extern __shared__ char smraw[];
    Smem* sm = reinterpret_cast<Smem*>(smraw);
    const int b = blockIdx.x;
    const int tid = threadIdx.x;

    // ---------------- Phase A: state encoder ----------------
    // Scratch overlays (regions not yet holding persistent data):
    float* Stile = reinterpret_cast<float*>(sm->W3T);  // 16 KB
    float* T1    = reinterpret_cast<float*>(sm->W2T);  // 16 KB

    const float* sb = s + (size_t)b * 64 * 64;
    for (int idx = tid; idx < 4096; idx += NTHREADS) Stile[idx] = sb[idx];
    __syncthreads();

    // T1 = relu(S @ se_w1 + se_b1)   [64,64]
    for (int ch = tid; ch < 64 * 16; ch += NTHREADS) {
        int r = ch >> 4, c0 = (ch & 15) << 2;
        const float* sr = &Stile[r * 64];
        float4 bb = *reinterpret_cast<const float4*>(se_b1 + c0);
        float a0 = bb.x, a1 = bb.y, a2 = bb.z, a3 = bb.w;
        #pragma unroll 8
        for (int k = 0; k < 64; k++) {
            float v = sr[k];
            float4 w = *reinterpret_cast<const float4*>(se_w1 + k * 64 + c0);
            a0 += v * w.x; a1 += v * w.y; a2 += v * w.z; a3 += v * w.w;
        }
        float* dst = &T1[r * 64 + c0];
        dst[0] = fmaxf(a0, 0.f); dst[1] = fmaxf(a1, 0.f);
        dst[2] = fmaxf(a2, 0.f); dst[3] = fmaxf(a3, 0.f);
    }
    __syncthreads();

    // H = relu(T1 @ se_w2 + se_b2)
    for (int ch = tid; ch < 64 * 16; ch += NTHREADS) {
        int r = ch >> 4, c0 = (ch & 15) << 2;
        const float* tr = &T1[r * 64];
        float4 bb = *reinterpret_cast<const float4*>(se_b2 + c0);
        float a0 = bb.x, a1 = bb.y, a2 = bb.z, a3 = bb.w;
        #pragma unroll 8
        for (int k = 0; k < 64; k++) {
            float v = tr[k];
            float4 w = *reinterpret_cast<const float4*>(se_w2 + k * 64 + c0);
            a0 += v * w.x; a1 += v * w.y; a2 += v * w.z; a3 += v * w.w;
        }
        sm->H[r][c0 + 0] = fmaxf(a0, 0.f); sm->H[r][c0 + 1] = fmaxf(a1, 0.f);
        sm->H[r][c0 + 2] = fmaxf(a2, 0.f); sm->H[r][c0 + 3] = fmaxf(a3, 0.f);
    }
    __syncthreads();

    // ---------------- Phase B: P1/P2/Q1/Q2 + weight staging ----------------
    if (tid < 64) { sm->hx[tid] = sm->H[tid][0]; sm->hy[tid] = sm->H[tid][1]; }
    if (tid < 128) {
        sm->w1L[tid]  = rc_w1[128 * 128 + tid];
        sm->b2s[tid]  = rc_b2[tid];
        sm->b3s[tid]  = rc_b3[tid];
        sm->ab2s[tid] = an_b2[tid];
        sm->accs[tid] = 0.f;
        sm->msum[tid] = 0.f;
    }
    if (tid < 64) sm->aw1L[tid] = an_w1[128 * 64 + tid];

    // P1[i][c] = sum_k H[i][k]*rc_w1[k][c] + rc_b1[c]
    for (int ch = tid; ch < 64 * 32; ch += NTHREADS) {
        int i = ch >> 5, c0 = (ch & 31) << 2;
        const float* hr = sm->H[i];
        float4 bb = *reinterpret_cast<const float4*>(rc_b1 + c0);
        float a0 = bb.x, a1 = bb.y, a2 = bb.z, a3 = bb.w;
        #pragma unroll 8
        for (int k = 0; k < 64; k++) {
            float v = hr[k];
            float4 w = *reinterpret_cast<const float4*>(rc_w1 + k * 128 + c0);
            a0 += v * w.x; a1 += v * w.y; a2 += v * w.z; a3 += v * w.w;
        }
        sm->P1[i][c0] = a0; sm->P1[i][c0 + 1] = a1;
        sm->P1[i][c0 + 2] = a2; sm->P1[i][c0 + 3] = a3;
    }
    // P2[j][c] = sum_k H[j][k]*rc_w1[64+k][c]
    for (int ch = tid; ch < 64 * 32; ch += NTHREADS) {
        int i = ch >> 5, c0 = (ch & 31) << 2;
        const float* hr = sm->H[i];
        float a0 = 0.f, a1 = 0.f, a2 = 0.f, a3 = 0.f;
        #pragma unroll 8
        for (int k = 0; k < 64; k++) {
            float v = hr[k];
            float4 w = *reinterpret_cast<const float4*>(rc_w1 + (64 + k) * 128 + c0);
            a0 += v * w.x; a1 += v * w.y; a2 += v * w.z; a3 += v * w.w;
        }
        sm->P2[i][c0] = a0; sm->P2[i][c0 + 1] = a1;
        sm->P2[i][c0 + 2] = a2; sm->P2[i][c0 + 3] = a3;
    }
    // Q1 / Q2 (att layer-1)
    for (int ch = tid; ch < 64 * 16; ch += NTHREADS) {
        int i = ch >> 4, c0 = (ch & 15) << 2;
        const float* hr = sm->H[i];
        float4 bb = *reinterpret_cast<const float4*>(an_b1 + c0);
        float a0 = bb.x, a1 = bb.y, a2 = bb.z, a3 = bb.w;
        #pragma unroll 8
        for (int k = 0; k < 64; k++) {
            float v = hr[k];
            float4 w = *reinterpret_cast<const float4*>(an_w1 + k * 64 + c0);
            a0 += v * w.x; a1 += v * w.y; a2 += v * w.z; a3 += v * w.w;
        }
        sm->Q1[i][c0] = a0; sm->Q1[i][c0 + 1] = a1;
        sm->Q1[i][c0 + 2] = a2; sm->Q1[i][c0 + 3] = a3;
    }
    for (int ch = tid; ch < 64 * 16; ch += NTHREADS) {
        int i = ch >> 4, c0 = (ch & 15) << 2;
        const float* hr = sm->H[i];
        float a0 = 0.f, a1 = 0.f, a2 = 0.f, a3 = 0.f;
        #pragma unroll 8
        for (int k = 0; k < 64; k++) {
            float v = hr[k];
            float4 w = *reinterpret_cast<const float4*>(an_w1 + (64 + k) * 64 + c0);
            a0 += v * w.x; a1 += v * w.y; a2 += v * w.z; a3 += v * w.w;
        }
        sm->Q2[i][c0] = a0; sm->Q2[i][c0 + 1] = a1;
        sm->Q2[i][c0 + 2] = a2; sm->Q2[i][c0 + 3] = a3;
    }
    __syncthreads();  // T1/Stile (overlaying W2T/W3T) fully consumed

    // Stage transposed fp16 weights (coalesced gmem read, padded smem write)
    for (int idx = tid; idx < 16384; idx += NTHREADS) {
        int k = idx >> 7, n = idx & 127;
        sm->W2T[n][k] = __float2half(rc_w2[idx]);
        sm->W3T[n][k] = __float2half(rc_w3[idx]);
    }
    for (int idx = tid; idx < 8192; idx += NTHREADS) {
        int k = idx >> 7, n = idx & 127;
        sm->AW2T[n][k] = __float2half(an_w2[idx]);
    }
    __syncthreads();

    // ---------------- Main loop: pairwise MLP via mma ----------------
    const int warp = tid >> 5;
    const int lane = tid & 31;
    const int g  = lane >> 2;   // group id (row within 8)
    const int t4 = lane & 3;    // thread-in-group (col pair)

    for (int slab = warp; slab < 256; slab += NWARPS) {
        const int i  = slab >> 2;
        const int j0 = (slab & 3) << 4;
        const int jA = j0 + g;
        const int jB = jA + 8;

        const float dxA = sm->hx[i] - sm->hx[jA], dyA = sm->hy[i] - sm->hy[jA];
        const float dxB = sm->hx[i] - sm->hx[jB], dyB = sm->hy[i] - sm->hy[jB];
        const float dA = dxA * dxA + dyA * dyA;
        const float dB = dxB * dxB + dyB * dyB;

        const float* P1i = sm->P1[i];
        const float* P2a = sm->P2[jA];
        const float* P2b = sm->P2[jB];

        unsigned af[8][4];
        // x1 = relu(P1[i] + P2[j] + dist*w1L), built directly as A fragments
        #pragma unroll
        for (int kk = 0; kk < 8; kk++) {
            int c = kk * 16 + t4 * 2;
            float w0 = sm->w1L[c],     w1 = sm->w1L[c + 1];
            float w8 = sm->w1L[c + 8], w9 = sm->w1L[c + 9];
            float p0 = P1i[c], p1 = P1i[c + 1], p8 = P1i[c + 8], p9 = P1i[c + 9];
            af[kk][0] = pack2(fmaxf(p0 + P2a[c]     + dA * w0, 0.f),
                              fmaxf(p1 + P2a[c + 1] + dA * w1, 0.f));
            af[kk][1] = pack2(fmaxf(p0 + P2b[c]     + dB * w0, 0.f),
                              fmaxf(p1 + P2b[c + 1] + dB * w1, 0.f));
            af[kk][2] = pack2(fmaxf(p8 + P2a[c + 8] + dA * w8, 0.f),
                              fmaxf(p9 + P2a[c + 9] + dA * w9, 0.f));
            af[kk][3] = pack2(fmaxf(p8 + P2b[c + 8] + dB * w8, 0.f),
                              fmaxf(p9 + P2b[c + 9] + dB * w9, 0.f));
        }

        // GEMM1: x2pre = x1 @ rc_w2
        float x[16][4];
        #pragma unroll
        for (int nt = 0; nt < 16; nt++) {
            x[nt][0] = x[nt][1] = x[nt][2] = x[nt][3] = 0.f;
            const __half* wrow = &sm->W2T[nt * 8 + g][0];
            #pragma unroll
            for (int kk = 0; kk < 8; kk++) {
                unsigned b0 = *reinterpret_cast<const unsigned*>(wrow + kk * 16 + t4 * 2);
                unsigned b1 = *reinterpret_cast<const unsigned*>(wrow + kk * 16 + t4 * 2 + 8);
                mma16816(x[nt], af[kk], b0, b1);
            }
        }

        // relu(+bias), repack C-fragments -> A-fragments (register-local)
        #pragma unroll
        for (int kk = 0; kk < 8; kk++) {
            int c = kk * 16 + t4 * 2;
            float b20 = sm->b2s[c],     b21 = sm->b2s[c + 1];
            float b28 = sm->b2s[c + 8], b29 = sm->b2s[c + 9];
            af[kk][0] = pack2(fmaxf(x[2*kk][0]   + b20, 0.f), fmaxf(x[2*kk][1]   + b21, 0.f));
            af[kk][1] = pack2(fmaxf(x[2*kk][2]   + b20, 0.f), fmaxf(x[2*kk][3]   + b21, 0.f));
            af[kk][2] = pack2(fmaxf(x[2*kk+1][0] + b28, 0.f), fmaxf(x[2*kk+1][1] + b29, 0.f));
            af[kk][3] = pack2(fmaxf(x[2*kk+1][2] + b28, 0.f), fmaxf(x[2*kk+1][3] + b29, 0.f));
        }

        // GEMM2: rel = relu(x2 @ rc_w3 + b3)
        float rel[16][4];
        #pragma unroll
        for (int nt = 0; nt < 16; nt++) {
            rel[nt][0] = rel[nt][1] = rel[nt][2] = rel[nt][3] = 0.f;
            const __half* wrow = &sm->W3T[nt * 8 + g][0];
            #pragma unroll
            for (int kk = 0; kk < 8; kk++) {
                unsigned b0 = *reinterpret_cast<const unsigned*>(wrow + kk * 16 + t4 * 2);
                unsigned b1 = *reinterpret_cast<const unsigned*>(wrow + kk * 16 + t4 * 2 + 8);
                mma16816(rel[nt], af[kk], b0, b1);
            }
        }
        #pragma unroll
        for (int nt = 0; nt < 16; nt++) {
            int c0 = nt * 8 + t4 * 2;
            rel[nt][0] = fmaxf(rel[nt][0] + sm->b3s[c0], 0.f);
            rel[nt][1] = fmaxf(rel[nt][1] + sm->b3s[c0 + 1], 0.f);
            rel[nt][2] = fmaxf(rel[nt][2] + sm->b3s[c0], 0.f);
            rel[nt][3] = fmaxf(rel[nt][3] + sm->b3s[c0 + 1], 0.f);
        }

        // Attention path: a1 = relu(Q1[i] + Q2[j] + dist*aw1L)  [16,64]
        {
            const float* Q1i = sm->Q1[i];
            const float* Q2a = sm->Q2[jA];
            const float* Q2b = sm->Q2[jB];
            #pragma unroll
            for (int kk = 0; kk < 4; kk++) {
                int c = kk * 16 + t4 * 2;
                float w0 = sm->aw1L[c],     w1 = sm->aw1L[c + 1];
                float w8 = sm->aw1L[c + 8], w9 = sm->aw1L[c + 9];
                float q0 = Q1i[c], q1 = Q1i[c + 1], q8 = Q1i[c + 8], q9 = Q1i[c + 9];
                af[kk][0] = pack2(fmaxf(q0 + Q2a[c]     + dA * w0, 0.f),
                                  fmaxf(q1 + Q2a[c + 1] + dA * w1, 0.f));
                af[kk][1] = pack2(fmaxf(q0 + Q2b[c]     + dB * w0, 0.f),
                                  fmaxf(q1 + Q2b[c + 1] + dB * w1, 0.f));
                af[kk][2] = pack2(fmaxf(q8 + Q2a[c + 8] + dA * w8, 0.f),
                                  fmaxf(q9 + Q2a[c + 9] + dA * w9, 0.f));
                af[kk][3] = pack2(fmaxf(q8 + Q2b[c + 8] + dB * w8, 0.f),
                                  fmaxf(q9 + Q2b[c + 9] + dB * w9, 0.f));
            }
        }

        // GEMM att: attpre = a1 @ an_w2
        #pragma unroll
        for (int nt = 0; nt < 16; nt++) {
            x[nt][0] = x[nt][1] = x[nt][2] = x[nt][3] = 0.f;
            const __half* wrow = &sm->AW2T[nt * 8 + g][0];
            #pragma unroll
            for (int kk = 0; kk < 4; kk++) {
                unsigned b0 = *reinterpret_cast<const unsigned*>(wrow + kk * 16 + t4 * 2);
                unsigned b1 = *reinterpret_cast<const unsigned*>(wrow + kk * 16 + t4 * 2 + 8);
                mma16816(x[nt], af[kk], b0, b1);
            }
        }

        // sigmoid, multiply, reduce over all 16 pair-rows, accumulate
        #pragma unroll
        for (int nt = 0; nt < 16; nt++) {
            int c0 = nt * 8 + t4 * 2;
            float s0 = 1.f / (1.f + __expf(-(x[nt][0] + sm->ab2s[c0])));
            float s1 = 1.f / (1.f + __expf(-(x[nt][1] + sm->ab2s[c0 + 1])));
            float s2 = 1.f / (1.f + __expf(-(x[nt][2] + sm->ab2s[c0])));
            float s3 = 1.f / (1.f + __expf(-(x[nt][3] + sm->ab2s[c0 + 1])));
            float v0 = rel[nt][0] * s0 + rel[nt][2] * s2;
            float v1 = rel[nt][1] * s1 + rel[nt][3] * s3;
            v0 += __shfl_xor_sync(0xffffffffu, v0, 4);
            v0 += __shfl_xor_sync(0xffffffffu, v0, 8);
            v0 += __shfl_xor_sync(0xffffffffu, v0, 16);
            v1 += __shfl_xor_sync(0xffffffffu, v1, 4);
            v1 += __shfl_xor_sync(0xffffffffu, v1, 8);
            v1 += __shfl_xor_sync(0xffffffffu, v1, 16);
            if (lane < 4) {
                atomicAdd(&sm->accs[c0], v0);
                atomicAdd(&sm->accs[c0 + 1], v1);
            }
        }
    }
    __syncthreads();

    // ---------------- Epilogue: self_dyn + final mean ----------------
    // msum[c] = sum_i relu(h_i @ sd_w1 + sd_b1)[c]
    float* SW1 = reinterpret_cast<float*>(sm->W2T);  // reuse (32 KB)
    for (int idx = tid; idx < 8192; idx += NTHREADS) SW1[idx] = sd_w1[idx];
    __syncthreads();
    {
        int c = tid & 127, hh = tid >> 7;
        float a = 0.f;
        for (int i = hh * 32; i < hh * 32 + 32; i++) {
            const float* hr = sm->H[i];
            float u = sd_b1[c];
            #pragma unroll 8
            for (int k = 0; k < 64; k++) u += hr[k] * SW1[k * 128 + c];
            a += fmaxf(u, 0.f);
        }
        atomicAdd(&sm->msum[c], a);
    }
    __syncthreads();
    if (tid < 128) {
        // out[b][c] = (msum/64) @ sd_w2 + sd_b2 + accs/4096
        // NOTE: contraction is over 2cl = 128 dims (sd_w2 is 128x128).
        float r = sd_b2[tid] + sm->accs[tid] * (1.f / 4096.f);
        #pragma unroll 8
        for (int k = 0; k < 128; k++)
            r += (sm->msum[k] * (1.f / 64.f)) * sd_w2[k * 128 + tid];
        out[(size_t)b * 128 + tid] = r;
    }
}

extern "C" void kernel_launch(void* const* d_in, const int* in_sizes, int n_in,
                              void* d_out, int out_size) {
    (void)in_sizes; (void)n_in; (void)out_size;
    cudaFuncSetAttribute(sgh_kernel, cudaFuncAttributeMaxDynamicSharedMemorySize,
                         (int)sizeof(Smem));
    const float* s     = (const float*)d_in[0];
    const float* se_w1 = (const float*)d_in[1];
    const float* se_b1 = (const float*)d_in[2];
    const float* se_w2 = (const float*)d_in[3];
    const float* se_b2 = (const float*)d_in[4];
    const float* sd_w1 = (const float*)d_in[5];
    const float* sd_b1 = (const float*)d_in[6];
    const float* sd_w2 = (const float*)d_in[7];
    const float* sd_b2 = (const float*)d_in[8];
    const float* rc_w1 = (const float*)d_in[9];
    const float* rc_b1 = (const float*)d_in[10];
    const float* rc_w2 = (const float*)d_in[11];
    const float* rc_b2 = (const float*)d_in[12];
    const float* rc_w3 = (const float*)d_in[13];
    const float* rc_b3 = (const float*)d_in[14];
    const float* an_w1 = (const float*)d_in[15];
    const float* an_b1 = (const float*)d_in[16];
    const float* an_w2 = (const float*)d_in[17];
    const float* an_b2 = (const float*)d_in[18];

    sgh_kernel<<<128, NTHREADS, sizeof(Smem)>>>(
        s, se_w1, se_b1, se_w2, se_b2, sd_w1, sd_b1, sd_w2, sd_b2,
        rc_w1, rc_b1, rc_w2, rc_b2, rc_w3, rc_b3,
        an_w1, an_b1, an_w2, an_b2, (float*)d_out);
}

// round 3
// speedup vs baseline: 1.3486x; 1.3486x over previous
#include <cuda_runtime.h>
#include <cuda_fp16.h>

// SimpleGraphHead fused kernel, round 3.
// B=128 batches, N=64 objects, cl=64, 2cl=128. One CTA per batch.
// Pairwise MLP with mma.sync.m16n8k16; B operands via ldmatrix.x4;
// att-first + fused GEMM2 reduction to cut registers; 12 warps.

#define NWARPS 12
#define NTHREADS 384

struct Smem {
    float H[64][64];        // state-encoder output h[b]  (16 KB)
    float P1[64][128];      // h@rc_w1[:64] + rc_b1       (32 KB)
    float P2[64][132];      // h@rc_w1[64:128]  (padded)  (33 KB)
    float Q1[64][64];       // h@an_w1[:64] + an_b1       (16 KB)
    float Q2[64][68];       // h@an_w1[64:128]  (padded)  (17 KB)
    __half W2T[128][136];   // rc_w2 transposed, padded   (34 KB) row=272B (17*16)
    __half W3T[128][136];   // rc_w3 transposed, padded   (34 KB)
    __half AW2T[128][72];   // an_w2 transposed, padded   (18 KB) row=144B (9*16)
    float w1L[128];         // rc_w1[128,:]  (dist row)
    float aw1L[64];         // an_w1[128,:]
    float b2s[128], b3s[128], ab2s[128];
    float hx[64], hy[64];
    float accs[128];        // sum over all pairs of rel*att
    float msum[128];        // sum_i relu(h_i@sd_w1 + sd_b1)
};

__device__ __forceinline__ unsigned pack2(float x, float y) {
    __half2 h = __floats2half2_rn(x, y);
    return *reinterpret_cast<unsigned*>(&h);
}

__device__ __forceinline__ void mma16816(float* d, const unsigned* a,
                                         unsigned b0, unsigned b1) {
    asm volatile(
        "mma.sync.aligned.m16n8k16.row.col.f32.f16.f16.f32 "
        "{%0,%1,%2,%3}, {%4,%5,%6,%7}, {%8,%9}, {%0,%1,%2,%3};\n"
        : "+f"(d[0]), "+f"(d[1]), "+f"(d[2]), "+f"(d[3])
        : "r"(a[0]), "r"(a[1]), "r"(a[2]), "r"(a[3]), "r"(b0), "r"(b1));
}

__device__ __forceinline__ void ldm_x4(unsigned& r0, unsigned& r1,
                                       unsigned& r2, unsigned& r3,
                                       unsigned saddr) {
    asm volatile("ldmatrix.sync.aligned.m8n8.x4.shared.b16 {%0,%1,%2,%3}, [%4];"
                 : "=r"(r0), "=r"(r1), "=r"(r2), "=r"(r3) : "r"(saddr));
}

__global__ void __launch_bounds__(NTHREADS, 1)
sgh_kernel(const float* __restrict__ s,
           const float* __restrict__ se_w1, const float* __restrict__ se_b1,
           const float* __restrict__ se_w2, const float* __restrict__ se_b2,
           const float* __restrict__ sd_w1, const float* __restrict__ sd_b1,
           const float* __restrict__ sd_w2, const float* __restrict__ sd_b2,
           const float* __restrict__ rc_w1, const float* __restrict__ rc_b1,
           const float* __restrict__ rc_w2, const float* __restrict__ rc_b2,
           const float* __restrict__ rc_w3, const float* __restrict__ rc_b3,
           const float* __restrict__ an_w1, const float* __restrict__ an_b1,
           const float* __restrict__ an_w2, const float* __restrict__ an_b2,
           float* __restrict__ out) {
    extern __shared__ char smraw[];
    Smem* sm = reinterpret_cast<Smem*>(smraw);
    const int b = blockIdx.x;
    const int tid = threadIdx.x;

    // ---------------- Phase A: state encoder ----------------
    float* Stile = reinterpret_cast<float*>(sm->W3T);  // scratch overlay
    float* T1    = reinterpret_cast<float*>(sm->W2T);  // scratch overlay

    const float* sb = s + (size_t)b * 64 * 64;
    for (int idx = tid; idx < 4096; idx += NTHREADS) Stile[idx] = sb[idx];
    __syncthreads();

    for (int ch = tid; ch < 64 * 16; ch += NTHREADS) {
        int r = ch >> 4, c0 = (ch & 15) << 2;
        const float* sr = &Stile[r * 64];
        float4 bb = *reinterpret_cast<const float4*>(se_b1 + c0);
        float a0 = bb.x, a1 = bb.y, a2 = bb.z, a3 = bb.w;
        #pragma unroll 8
        for (int k = 0; k < 64; k++) {
            float v = sr[k];
            float4 w = *reinterpret_cast<const float4*>(se_w1 + k * 64 + c0);
            a0 += v * w.x; a1 += v * w.y; a2 += v * w.z; a3 += v * w.w;
        }
        float* dst = &T1[r * 64 + c0];
        dst[0] = fmaxf(a0, 0.f); dst[1] = fmaxf(a1, 0.f);
        dst[2] = fmaxf(a2, 0.f); dst[3] = fmaxf(a3, 0.f);
    }
    __syncthreads();

    for (int ch = tid; ch < 64 * 16; ch += NTHREADS) {
        int r = ch >> 4, c0 = (ch & 15) << 2;
        const float* tr = &T1[r * 64];
        float4 bb = *reinterpret_cast<const float4*>(se_b2 + c0);
        float a0 = bb.x, a1 = bb.y, a2 = bb.z, a3 = bb.w;
        #pragma unroll 8
        for (int k = 0; k < 64; k++) {
            float v = tr[k];
            float4 w = *reinterpret_cast<const float4*>(se_w2 + k * 64 + c0);
            a0 += v * w.x; a1 += v * w.y; a2 += v * w.z; a3 += v * w.w;
        }
        sm->H[r][c0 + 0] = fmaxf(a0, 0.f); sm->H[r][c0 + 1] = fmaxf(a1, 0.f);
        sm->H[r][c0 + 2] = fmaxf(a2, 0.f); sm->H[r][c0 + 3] = fmaxf(a3, 0.f);
    }
    __syncthreads();

    // ---------------- Phase B: P1/P2/Q1/Q2 + weight staging ----------------
    if (tid < 64) { sm->hx[tid] = sm->H[tid][0]; sm->hy[tid] = sm->H[tid][1]; }
    if (tid < 128) {
        sm->w1L[tid]  = rc_w1[128 * 128 + tid];
        sm->b2s[tid]  = rc_b2[tid];
        sm->b3s[tid]  = rc_b3[tid];
        sm->ab2s[tid] = an_b2[tid];
        sm->accs[tid] = 0.f;
        sm->msum[tid] = 0.f;
    }
    if (tid < 64) sm->aw1L[tid] = an_w1[128 * 64 + tid];

    for (int ch = tid; ch < 64 * 32; ch += NTHREADS) {
        int i = ch >> 5, c0 = (ch & 31) << 2;
        const float* hr = sm->H[i];
        float4 bb = *reinterpret_cast<const float4*>(rc_b1 + c0);
        float a0 = bb.x, a1 = bb.y, a2 = bb.z, a3 = bb.w;
        #pragma unroll 8
        for (int k = 0; k < 64; k++) {
            float v = hr[k];
            float4 w = *reinterpret_cast<const float4*>(rc_w1 + k * 128 + c0);
            a0 += v * w.x; a1 += v * w.y; a2 += v * w.z; a3 += v * w.w;
        }
        sm->P1[i][c0] = a0; sm->P1[i][c0 + 1] = a1;
        sm->P1[i][c0 + 2] = a2; sm->P1[i][c0 + 3] = a3;
    }
    for (int ch = tid; ch < 64 * 32; ch += NTHREADS) {
        int i = ch >> 5, c0 = (ch & 31) << 2;
        const float* hr = sm->H[i];
        float a0 = 0.f, a1 = 0.f, a2 = 0.f, a3 = 0.f;
        #pragma unroll 8
        for (int k = 0; k < 64; k++) {
            float v = hr[k];
            float4 w = *reinterpret_cast<const float4*>(rc_w1 + (64 + k) * 128 + c0);
            a0 += v * w.x; a1 += v * w.y; a2 += v * w.z; a3 += v * w.w;
        }
        sm->P2[i][c0] = a0; sm->P2[i][c0 + 1] = a1;
        sm->P2[i][c0 + 2] = a2; sm->P2[i][c0 + 3] = a3;
    }
    for (int ch = tid; ch < 64 * 16; ch += NTHREADS) {
        int i = ch >> 4, c0 = (ch & 15) << 2;
        const float* hr = sm->H[i];
        float4 bb = *reinterpret_cast<const float4*>(an_b1 + c0);
        float a0 = bb.x, a1 = bb.y, a2 = bb.z, a3 = bb.w;
        #pragma unroll 8
        for (int k = 0; k < 64; k++) {
            float v = hr[k];
            float4 w = *reinterpret_cast<const float4*>(an_w1 + k * 64 + c0);
            a0 += v * w.x; a1 += v * w.y; a2 += v * w.z; a3 += v * w.w;
        }
        sm->Q1[i][c0] = a0; sm->Q1[i][c0 + 1] = a1;
        sm->Q1[i][c0 + 2] = a2; sm->Q1[i][c0 + 3] = a3;
    }
    for (int ch = tid; ch < 64 * 16; ch += NTHREADS) {
        int i = ch >> 4, c0 = (ch & 15) << 2;
        const float* hr = sm->H[i];
        float a0 = 0.f, a1 = 0.f, a2 = 0.f, a3 = 0.f;
        #pragma unroll 8
        for (int k = 0; k < 64; k++) {
            float v = hr[k];
            float4 w = *reinterpret_cast<const float4*>(an_w1 + (64 + k) * 64 + c0);
            a0 += v * w.x; a1 += v * w.y; a2 += v * w.z; a3 += v * w.w;
        }
        sm->Q2[i][c0] = a0; sm->Q2[i][c0 + 1] = a1;
        sm->Q2[i][c0 + 2] = a2; sm->Q2[i][c0 + 3] = a3;
    }
    __syncthreads();  // scratch overlays fully consumed

    for (int idx = tid; idx < 16384; idx += NTHREADS) {
        int k = idx >> 7, n = idx & 127;
        sm->W2T[n][k] = __float2half(rc_w2[idx]);
        sm->W3T[n][k] = __float2half(rc_w3[idx]);
    }
    for (int idx = tid; idx < 8192; idx += NTHREADS) {
        int k = idx >> 7, n = idx & 127;
        sm->AW2T[n][k] = __float2half(an_w2[idx]);
    }
    __syncthreads();

    // ---------------- Main loop ----------------
    const int warp = tid >> 5;
    const int lane = tid & 31;
    const int g  = lane >> 2;
    const int t4 = lane & 3;
    const int trow = lane & 7;
    const int tileid = lane >> 3;

    const unsigned offW = (unsigned)(trow * 272 + tileid * 16);
    const unsigned offA = (unsigned)(trow * 144 + tileid * 16);
    const unsigned baseW2 = (unsigned)__cvta_generic_to_shared(&sm->W2T[0][0]) + offW;
    const unsigned baseW3 = (unsigned)__cvta_generic_to_shared(&sm->W3T[0][0]) + offW;
    const unsigned baseAW = (unsigned)__cvta_generic_to_shared(&sm->AW2T[0][0]) + offA;

    float vacc0[16], vacc1[16];
    #pragma unroll
    for (int nt = 0; nt < 16; nt++) { vacc0[nt] = 0.f; vacc1[nt] = 0.f; }

    unsigned satt0[16], satt1[16];
    unsigned af[8][4], af2[8][4];

    for (int slab = warp; slab < 256; slab += NWARPS) {
        const int i  = slab >> 2;
        const int j0 = (slab & 3) << 4;
        const int jA = j0 + g;
        const int jB = jA + 8;

        const float dxA = sm->hx[i] - sm->hx[jA], dyA = sm->hy[i] - sm->hy[jA];
        const float dxB = sm->hx[i] - sm->hx[jB], dyB = sm->hy[i] - sm->hy[jB];
        const float dA = dxA * dxA + dyA * dyA;
        const float dB = dxB * dxB + dyB * dyB;

        // ---- attention path first ----
        {
            const float* Q1i = sm->Q1[i];
            const float* Q2a = sm->Q2[jA];
            const float* Q2b = sm->Q2[jB];
            #pragma unroll
            for (int kk = 0; kk < 4; kk++) {
                int c = kk * 16 + t4 * 2;
                float w0 = sm->aw1L[c],     w1 = sm->aw1L[c + 1];
                float w8 = sm->aw1L[c + 8], w9 = sm->aw1L[c + 9];
                float q0 = Q1i[c], q1 = Q1i[c + 1], q8 = Q1i[c + 8], q9 = Q1i[c + 9];
                af[kk][0] = pack2(fmaxf(q0 + Q2a[c]     + dA * w0, 0.f),
                                  fmaxf(q1 + Q2a[c + 1] + dA * w1, 0.f));
                af[kk][1] = pack2(fmaxf(q0 + Q2b[c]     + dB * w0, 0.f),
                                  fmaxf(q1 + Q2b[c + 1] + dB * w1, 0.f));
                af[kk][2] = pack2(fmaxf(q8 + Q2a[c + 8] + dA * w8, 0.f),
                                  fmaxf(q9 + Q2a[c + 9] + dA * w9, 0.f));
                af[kk][3] = pack2(fmaxf(q8 + Q2b[c + 8] + dB * w8, 0.f),
                                  fmaxf(q9 + Q2b[c + 9] + dB * w9, 0.f));
            }
        }
        #pragma unroll
        for (int nt = 0; nt < 16; nt++) {
            float d4[4] = {0.f, 0.f, 0.f, 0.f};
            #pragma unroll
            for (int kk2 = 0; kk2 < 2; kk2++) {
                unsigned r0, r1, r2, r3;
                ldm_x4(r0, r1, r2, r3, baseAW + nt * 1152 + kk2 * 64);
                mma16816(d4, af[2 * kk2],     r0, r1);
                mma16816(d4, af[2 * kk2 + 1], r2, r3);
            }
            int c0 = nt * 8 + t4 * 2;
            float ab0 = sm->ab2s[c0], ab1 = sm->ab2s[c0 + 1];
            float s0 = __frcp_rn(1.f + __expf(-(d4[0] + ab0)));
            float s1 = __frcp_rn(1.f + __expf(-(d4[1] + ab1)));
            float s2 = __frcp_rn(1.f + __expf(-(d4[2] + ab0)));
            float s3 = __frcp_rn(1.f + __expf(-(d4[3] + ab1)));
            satt0[nt] = pack2(s0, s1);
            satt1[nt] = pack2(s2, s3);
        }

        // ---- rel layer-1 fragments ----
        {
            const float* P1i = sm->P1[i];
            const float* P2a = sm->P2[jA];
            const float* P2b = sm->P2[jB];
            #pragma unroll
            for (int kk = 0; kk < 8; kk++) {
                int c = kk * 16 + t4 * 2;
                float w0 = sm->w1L[c],     w1 = sm->w1L[c + 1];
                float w8 = sm->w1L[c + 8], w9 = sm->w1L[c + 9];
                float p0 = P1i[c], p1 = P1i[c + 1], p8 = P1i[c + 8], p9 = P1i[c + 9];
                af[kk][0] = pack2(fmaxf(p0 + P2a[c]     + dA * w0, 0.f),
                                  fmaxf(p1 + P2a[c + 1] + dA * w1, 0.f));
                af[kk][1] = pack2(fmaxf(p0 + P2b[c]     + dB * w0, 0.f),
                                  fmaxf(p1 + P2b[c + 1] + dB * w1, 0.f));
                af[kk][2] = pack2(fmaxf(p8 + P2a[c + 8] + dA * w8, 0.f),
                                  fmaxf(p9 + P2a[c + 9] + dA * w9, 0.f));
                af[kk][3] = pack2(fmaxf(p8 + P2b[c + 8] + dB * w8, 0.f),
                                  fmaxf(p9 + P2b[c + 9] + dB * w9, 0.f));
            }
        }

        // ---- GEMM1, completed per nt-pair, packed straight into af2 ----
        #pragma unroll
        for (int p = 0; p < 8; p++) {
            float xA[4] = {0.f, 0.f, 0.f, 0.f};
            float xB[4] = {0.f, 0.f, 0.f, 0.f};
            #pragma unroll
            for (int kk2 = 0; kk2 < 4; kk2++) {
                unsigned a0, a1, a2, a3;
                ldm_x4(a0, a1, a2, a3, baseW2 + (2 * p) * 2176 + kk2 * 64);
                mma16816(xA, af[2 * kk2],     a0, a1);
                mma16816(xA, af[2 * kk2 + 1], a2, a3);
                ldm_x4(a0, a1, a2, a3, baseW2 + (2 * p + 1) * 2176 + kk2 * 64);
                mma16816(xB, af[2 * kk2],     a0, a1);
                mma16816(xB, af[2 * kk2 + 1], a2, a3);
            }
            int c = p * 16 + t4 * 2;
            float b20 = sm->b2s[c],     b21 = sm->b2s[c + 1];
            float b28 = sm->b2s[c + 8], b29 = sm->b2s[c + 9];
            af2[p][0] = pack2(fmaxf(xA[0] + b20, 0.f), fmaxf(xA[1] + b21, 0.f));
            af2[p][1] = pack2(fmaxf(xA[2] + b20, 0.f), fmaxf(xA[3] + b21, 0.f));
            af2[p][2] = pack2(fmaxf(xB[0] + b28, 0.f), fmaxf(xB[1] + b29, 0.f));
            af2[p][3] = pack2(fmaxf(xB[2] + b28, 0.f), fmaxf(xB[3] + b29, 0.f));
        }

        // ---- GEMM2 fused with rel*att accumulation ----
        #pragma unroll
        for (int nt = 0; nt < 16; nt++) {
            float d4[4] = {0.f, 0.f, 0.f, 0.f};
            #pragma unroll
            for (int kk2 = 0; kk2 < 4; kk2++) {
                unsigned r0, r1, r2, r3;
                ldm_x4(r0, r1, r2, r3, baseW3 + nt * 2176 + kk2 * 64);
                mma16816(d4, af2[2 * kk2],     r0, r1);
                mma16816(d4, af2[2 * kk2 + 1], r2, r3);
            }
            int c0 = nt * 8 + t4 * 2;
            float b30 = sm->b3s[c0], b31 = sm->b3s[c0 + 1];
            float r0 = fmaxf(d4[0] + b30, 0.f);
            float r1 = fmaxf(d4[1] + b31, 0.f);
            float r2 = fmaxf(d4[2] + b30, 0.f);
            float r3 = fmaxf(d4[3] + b31, 0.f);
            float2 sa = __half22float2(*reinterpret_cast<__half2*>(&satt0[nt]));
            float2 sb2 = __half22float2(*reinterpret_cast<__half2*>(&satt1[nt]));
            vacc0[nt] += r0 * sa.x + r2 * sb2.x;
            vacc1[nt] += r1 * sa.y + r3 * sb2.y;
        }
    }

    // ---- one reduction per warp ----
    #pragma unroll
    for (int nt = 0; nt < 16; nt++) {
        float v0 = vacc0[nt], v1 = vacc1[nt];
        v0 += __shfl_xor_sync(0xffffffffu, v0, 4);
        v0 += __shfl_xor_sync(0xffffffffu, v0, 8);
        v0 += __shfl_xor_sync(0xffffffffu, v0, 16);
        v1 += __shfl_xor_sync(0xffffffffu, v1, 4);
        v1 += __shfl_xor_sync(0xffffffffu, v1, 8);
        v1 += __shfl_xor_sync(0xffffffffu, v1, 16);
        if (lane < 4) {
            atomicAdd(&sm->accs[nt * 8 + lane * 2], v0);
            atomicAdd(&sm->accs[nt * 8 + lane * 2 + 1], v1);
        }
    }
    __syncthreads();

    // ---------------- Epilogue: self_dyn + final mean ----------------
    float* SW1 = reinterpret_cast<float*>(sm->W2T);  // reuse (32 KB)
    for (int idx = tid; idx < 8192; idx += NTHREADS) SW1[idx] = sd_w1[idx];
    __syncthreads();
    if (tid < 256) {
        int c = tid & 127, hh = tid >> 7;
        float a = 0.f;
        for (int i = hh * 32; i < hh * 32 + 32; i++) {
            const float* hr = sm->H[i];
            float u = sd_b1[c];
            #pragma unroll 8
            for (int k = 0; k < 64; k++) u += hr[k] * SW1[k * 128 + c];
            a += fmaxf(u, 0.f);
        }
        atomicAdd(&sm->msum[c], a);
    }
    __syncthreads();
    if (tid < 128) {
        // contraction over 2cl = 128 dims (sd_w2 is 128x128)
        float r = sd_b2[tid] + sm->accs[tid] * (1.f / 4096.f);
        #pragma unroll 8
        for (int k = 0; k < 128; k++)
            r += (sm->msum[k] * (1.f / 64.f)) * sd_w2[k * 128 + tid];
        out[(size_t)b * 128 + tid] = r;
    }
}

extern "C" void kernel_launch(void* const* d_in, const int* in_sizes, int n_in,
                              void* d_out, int out_size) {
    (void)in_sizes; (void)n_in; (void)out_size;
    cudaFuncSetAttribute(sgh_kernel, cudaFuncAttributeMaxDynamicSharedMemorySize,
                         (int)sizeof(Smem));
    const float* s     = (const float*)d_in[0];
    const float* se_w1 = (const float*)d_in[1];
    const float* se_b1 = (const float*)d_in[2];
    const float* se_w2 = (const float*)d_in[3];
    const float* se_b2 = (const float*)d_in[4];
    const float* sd_w1 = (const float*)d_in[5];
    const float* sd_b1 = (const float*)d_in[6];
    const float* sd_w2 = (const float*)d_in[7];
    const float* sd_b2 = (const float*)d_in[8];
    const float* rc_w1 = (const float*)d_in[9];
    const float* rc_b1 = (const float*)d_in[10];
    const float* rc_w2 = (const float*)d_in[11];
    const float* rc_b2 = (const float*)d_in[12];
    const float* rc_w3 = (const float*)d_in[13];
    const float* rc_b3 = (const float*)d_in[14];
    const float* an_w1 = (const float*)d_in[15];
    const float* an_b1 = (const float*)d_in[16];
    const float* an_w2 = (const float*)d_in[17];
    const float* an_b2 = (const float*)d_in[18];

    sgh_kernel<<<128, NTHREADS, sizeof(Smem)>>>(
        s, se_w1, se_b1, se_w2, se_b2, sd_w1, sd_b1, sd_w2, sd_b2,
        rc_w1, rc_b1, rc_w2, rc_b2, rc_w3, rc_b3,
        an_w1, an_b1, an_w2, an_b2, (float*)d_out);
}

// round 4
// speedup vs baseline: 2.1795x; 1.6161x over previous
#include <cuda_runtime.h>
#include <cuda_fp16.h>

// SimpleGraphHead fused kernel, round 4.
// B=128, N=64, cl=64. One CTA per batch, 16 warps.
// Layer-1 fragments built via ldmatrix from fp16 P/Q tables + HFMA2 corrections.
// GEMM2 + attention GEMM fused per-nt (two independent mma chains), tanh sigmoid.

#define NWARPS 16
#define NTHREADS 512

struct Smem {
    float  H[64][64];        // state-encoder output (fp32, for epilogue)
    __half P1h[64][136];     // h@rc_w1[:64] + rc_b1        row=272B
    __half P2h[64][136];     // h@rc_w1[64:128]             row=272B
    __half Q1h[64][72];      // h@an_w1[:64] + an_b1        row=144B
    __half Q2h[64][72];      // h@an_w1[64:128]             row=144B
    __half W2T[128][136];    // rc_w2^T                     row=272B
    __half W3T[128][136];    // rc_w3^T                     row=272B
    __half AW2T[128][72];    // an_w2^T                     row=144B
    __half w1Lh[128];        // rc_w1[128,:]
    __half aw1Lh[64];        // an_w1[128,:]
    float  b2s[128], b3s[128], ab2s[128];
    float  hx[64], hy[64];
    float  accs[128];
    float  msum[128];
};

__device__ __forceinline__ unsigned pack2(float x, float y) {
    __half2 h = __floats2half2_rn(x, y);
    return *reinterpret_cast<unsigned*>(&h);
}
__device__ __forceinline__ __half2 u2h(unsigned u) {
    return *reinterpret_cast<__half2*>(&u);
}
__device__ __forceinline__ unsigned h2u(__half2 h) {
    return *reinterpret_cast<unsigned*>(&h);
}
__device__ __forceinline__ float tanhfast(float x) {
    float y;
    asm("tanh.approx.f32 %0, %1;" : "=f"(y) : "f"(x));
    return y;
}
__device__ __forceinline__ void mma16816(float* d, const unsigned* a,
                                         unsigned b0, unsigned b1) {
    asm volatile(
        "mma.sync.aligned.m16n8k16.row.col.f32.f16.f16.f32 "
        "{%0,%1,%2,%3}, {%4,%5,%6,%7}, {%8,%9}, {%0,%1,%2,%3};\n"
        : "+f"(d[0]), "+f"(d[1]), "+f"(d[2]), "+f"(d[3])
        : "r"(a[0]), "r"(a[1]), "r"(a[2]), "r"(a[3]), "r"(b0), "r"(b1));
}
__device__ __forceinline__ void ldm_x4(unsigned& r0, unsigned& r1,
                                       unsigned& r2, unsigned& r3,
                                       unsigned saddr) {
    asm volatile("ldmatrix.sync.aligned.m8n8.x4.shared.b16 {%0,%1,%2,%3}, [%4];"
                 : "=r"(r0), "=r"(r1), "=r"(r2), "=r"(r3) : "r"(saddr));
}
// relu(p2frag + (d*w + base)) in half2
__device__ __forceinline__ unsigned frag_fix(unsigned p2f, unsigned d2,
                                             unsigned w, unsigned base,
                                             __half2 z2) {
    __half2 corr = __hfma2(u2h(d2), u2h(w), u2h(base));
    return h2u(__hmax2(__hadd2(u2h(p2f), corr), z2));
}

__global__ void __launch_bounds__(NTHREADS, 1)
sgh_kernel(const float* __restrict__ s,
           const float* __restrict__ se_w1, const float* __restrict__ se_b1,
           const float* __restrict__ se_w2, const float* __restrict__ se_b2,
           const float* __restrict__ sd_w1, const float* __restrict__ sd_b1,
           const float* __restrict__ sd_w2, const float* __restrict__ sd_b2,
           const float* __restrict__ rc_w1, const float* __restrict__ rc_b1,
           const float* __restrict__ rc_w2, const float* __restrict__ rc_b2,
           const float* __restrict__ rc_w3, const float* __restrict__ rc_b3,
           const float* __restrict__ an_w1, const float* __restrict__ an_b1,
           const float* __restrict__ an_w2, const float* __restrict__ an_b2,
           float* __restrict__ out) {
    extern __shared__ char smraw[];
    Smem* sm = reinterpret_cast<Smem*>(smraw);
    const int b = blockIdx.x;
    const int tid = threadIdx.x;

    // ---------------- Phase A: state encoder ----------------
    float* Stile = reinterpret_cast<float*>(sm->W3T);  // scratch overlay 16KB
    float* T1    = reinterpret_cast<float*>(sm->W2T);  // scratch overlay 16KB

    const float* sb = s + (size_t)b * 64 * 64;
    for (int idx = tid; idx < 4096; idx += NTHREADS) Stile[idx] = sb[idx];
    __syncthreads();

    for (int ch = tid; ch < 64 * 16; ch += NTHREADS) {
        int r = ch >> 4, c0 = (ch & 15) << 2;
        const float* sr = &Stile[r * 64];
        float4 bb = *reinterpret_cast<const float4*>(se_b1 + c0);
        float a0 = bb.x, a1 = bb.y, a2 = bb.z, a3 = bb.w;
        #pragma unroll 8
        for (int k = 0; k < 64; k++) {
            float v = sr[k];
            float4 w = *reinterpret_cast<const float4*>(se_w1 + k * 64 + c0);
            a0 += v * w.x; a1 += v * w.y; a2 += v * w.z; a3 += v * w.w;
        }
        float* dst = &T1[r * 64 + c0];
        dst[0] = fmaxf(a0, 0.f); dst[1] = fmaxf(a1, 0.f);
        dst[2] = fmaxf(a2, 0.f); dst[3] = fmaxf(a3, 0.f);
    }
    __syncthreads();

    for (int ch = tid; ch < 64 * 16; ch += NTHREADS) {
        int r = ch >> 4, c0 = (ch & 15) << 2;
        const float* tr = &T1[r * 64];
        float4 bb = *reinterpret_cast<const float4*>(se_b2 + c0);
        float a0 = bb.x, a1 = bb.y, a2 = bb.z, a3 = bb.w;
        #pragma unroll 8
        for (int k = 0; k < 64; k++) {
            float v = tr[k];
            float4 w = *reinterpret_cast<const float4*>(se_w2 + k * 64 + c0);
            a0 += v * w.x; a1 += v * w.y; a2 += v * w.z; a3 += v * w.w;
        }
        sm->H[r][c0 + 0] = fmaxf(a0, 0.f); sm->H[r][c0 + 1] = fmaxf(a1, 0.f);
        sm->H[r][c0 + 2] = fmaxf(a2, 0.f); sm->H[r][c0 + 3] = fmaxf(a3, 0.f);
    }
    __syncthreads();

    // ---------------- Phase B: P/Q tables (fp16) + biases ----------------
    if (tid < 64) { sm->hx[tid] = sm->H[tid][0]; sm->hy[tid] = sm->H[tid][1]; }
    if (tid < 128) {
        sm->w1Lh[tid] = __float2half(rc_w1[128 * 128 + tid]);
        sm->b2s[tid]  = rc_b2[tid];
        sm->b3s[tid]  = rc_b3[tid];
        sm->ab2s[tid] = an_b2[tid];
        sm->accs[tid] = 0.f;
        sm->msum[tid] = 0.f;
    }
    if (tid < 64) sm->aw1Lh[tid] = __float2half(an_w1[128 * 64 + tid]);

    for (int ch = tid; ch < 64 * 32; ch += NTHREADS) {
        int i = ch >> 5, c0 = (ch & 31) << 2;
        const float* hr = sm->H[i];
        float4 bb = *reinterpret_cast<const float4*>(rc_b1 + c0);
        float a0 = bb.x, a1 = bb.y, a2 = bb.z, a3 = bb.w;
        #pragma unroll 8
        for (int k = 0; k < 64; k++) {
            float v = hr[k];
            float4 w = *reinterpret_cast<const float4*>(rc_w1 + k * 128 + c0);
            a0 += v * w.x; a1 += v * w.y; a2 += v * w.z; a3 += v * w.w;
        }
        sm->P1h[i][c0]     = __float2half(a0);
        sm->P1h[i][c0 + 1] = __float2half(a1);
        sm->P1h[i][c0 + 2] = __float2half(a2);
        sm->P1h[i][c0 + 3] = __float2half(a3);
    }
    for (int ch = tid; ch < 64 * 32; ch += NTHREADS) {
        int i = ch >> 5, c0 = (ch & 31) << 2;
        const float* hr = sm->H[i];
        float a0 = 0.f, a1 = 0.f, a2 = 0.f, a3 = 0.f;
        #pragma unroll 8
        for (int k = 0; k < 64; k++) {
            float v = hr[k];
            float4 w = *reinterpret_cast<const float4*>(rc_w1 + (64 + k) * 128 + c0);
            a0 += v * w.x; a1 += v * w.y; a2 += v * w.z; a3 += v * w.w;
        }
        sm->P2h[i][c0]     = __float2half(a0);
        sm->P2h[i][c0 + 1] = __float2half(a1);
        sm->P2h[i][c0 + 2] = __float2half(a2);
        sm->P2h[i][c0 + 3] = __float2half(a3);
    }
    for (int ch = tid; ch < 64 * 16; ch += NTHREADS) {
        int i = ch >> 4, c0 = (ch & 15) << 2;
        const float* hr = sm->H[i];
        float4 bb = *reinterpret_cast<const float4*>(an_b1 + c0);
        float a0 = bb.x, a1 = bb.y, a2 = bb.z, a3 = bb.w;
        #pragma unroll 8
        for (int k = 0; k < 64; k++) {
            float v = hr[k];
            float4 w = *reinterpret_cast<const float4*>(an_w1 + k * 64 + c0);
            a0 += v * w.x; a1 += v * w.y; a2 += v * w.z; a3 += v * w.w;
        }
        sm->Q1h[i][c0]     = __float2half(a0);
        sm->Q1h[i][c0 + 1] = __float2half(a1);
        sm->Q1h[i][c0 + 2] = __float2half(a2);
        sm->Q1h[i][c0 + 3] = __float2half(a3);
    }
    for (int ch = tid; ch < 64 * 16; ch += NTHREADS) {
        int i = ch >> 4, c0 = (ch & 15) << 2;
        const float* hr = sm->H[i];
        float a0 = 0.f, a1 = 0.f, a2 = 0.f, a3 = 0.f;
        #pragma unroll 8
        for (int k = 0; k < 64; k++) {
            float v = hr[k];
            float4 w = *reinterpret_cast<const float4*>(an_w1 + (64 + k) * 64 + c0);
            a0 += v * w.x; a1 += v * w.y; a2 += v * w.z; a3 += v * w.w;
        }
        sm->Q2h[i][c0]     = __float2half(a0);
        sm->Q2h[i][c0 + 1] = __float2half(a1);
        sm->Q2h[i][c0 + 2] = __float2half(a2);
        sm->Q2h[i][c0 + 3] = __float2half(a3);
    }
    __syncthreads();  // scratch overlays fully consumed

    for (int idx = tid; idx < 16384; idx += NTHREADS) {
        int k = idx >> 7, n = idx & 127;
        sm->W2T[n][k] = __float2half(rc_w2[idx]);
        sm->W3T[n][k] = __float2half(rc_w3[idx]);
    }
    for (int idx = tid; idx < 8192; idx += NTHREADS) {
        int k = idx >> 7, n = idx & 127;
        sm->AW2T[n][k] = __float2half(an_w2[idx]);
    }
    __syncthreads();

    // ---------------- Main loop ----------------
    const int warp = tid >> 5;
    const int lane = tid & 31;
    const int g  = lane >> 2;
    const int t4 = lane & 3;
    const int trow = lane & 7;        // B-fragment ldmatrix row
    const int tileid = lane >> 3;     // B-fragment ldmatrix tile
    const int lrow  = lane & 15;      // A-fragment ldmatrix row
    const int lcol8 = (lane >> 4) << 3;

    const unsigned baseW2 = (unsigned)__cvta_generic_to_shared(&sm->W2T[0][0])
                            + trow * 272 + tileid * 16;
    const unsigned baseW3 = (unsigned)__cvta_generic_to_shared(&sm->W3T[0][0])
                            + trow * 272 + tileid * 16;
    const unsigned baseAW = (unsigned)__cvta_generic_to_shared(&sm->AW2T[0][0])
                            + trow * 144 + tileid * 16;
    const unsigned baseP2 = (unsigned)__cvta_generic_to_shared(&sm->P2h[0][0])
                            + lrow * 272 + lcol8 * 2;
    const unsigned baseQ2 = (unsigned)__cvta_generic_to_shared(&sm->Q2h[0][0])
                            + lrow * 144 + lcol8 * 2;

    const __half2 z2 = __floats2half2_rn(0.f, 0.f);

    float vacc0[16], vacc1[16];
    #pragma unroll
    for (int nt = 0; nt < 16; nt++) { vacc0[nt] = 0.f; vacc1[nt] = 0.f; }

    unsigned af[8][4];   // rel layer-1 fragments (transient), reused per phase
    unsigned af2[8][4];  // rel layer-2 input fragments
    unsigned afQ[4][4];  // att layer-1 fragments

    for (int slab = warp; slab < 256; slab += NWARPS) {
        const int i  = slab >> 2;
        const int j0 = (slab & 3) << 4;
        const int jA = j0 + g;
        const int jB = jA + 8;

        const float dxA = sm->hx[i] - sm->hx[jA], dyA = sm->hy[i] - sm->hy[jA];
        const float dxB = sm->hx[i] - sm->hx[jB], dyB = sm->hy[i] - sm->hy[jB];
        const unsigned dA2 = h2u(__float2half2_rn(dxA * dxA + dyA * dyA));
        const unsigned dB2 = h2u(__float2half2_rn(dxB * dxB + dyB * dyB));

        const unsigned addrP2 = baseP2 + j0 * 272;
        const unsigned addrQ2 = baseQ2 + j0 * 144;
        const __half* P1i = sm->P1h[i];
        const __half* Q1i = sm->Q1h[i];

        // ---- rel layer-1 fragments: ldmatrix(P2) + HFMA2 correction ----
        #pragma unroll
        for (int kk = 0; kk < 8; kk++) {
            const int c = kk * 16 + t4 * 2;
            unsigned w01 = *reinterpret_cast<const unsigned*>(&sm->w1Lh[c]);
            unsigned w89 = *reinterpret_cast<const unsigned*>(&sm->w1Lh[c + 8]);
            unsigned p01 = *reinterpret_cast<const unsigned*>(&P1i[c]);
            unsigned p89 = *reinterpret_cast<const unsigned*>(&P1i[c + 8]);
            unsigned f0, f1, f2, f3;
            ldm_x4(f0, f1, f2, f3, addrP2 + kk * 32);
            af[kk][0] = frag_fix(f0, dA2, w01, p01, z2);
            af[kk][1] = frag_fix(f1, dB2, w01, p01, z2);
            af[kk][2] = frag_fix(f2, dA2, w89, p89, z2);
            af[kk][3] = frag_fix(f3, dB2, w89, p89, z2);
        }

        // ---- GEMM1: x2 = relu(x1 @ rc_w2 + b2), packed into af2 ----
        #pragma unroll
        for (int p = 0; p < 8; p++) {
            float xA[4] = {0.f, 0.f, 0.f, 0.f};
            float xB[4] = {0.f, 0.f, 0.f, 0.f};
            #pragma unroll
            for (int kk2 = 0; kk2 < 4; kk2++) {
                unsigned a0, a1, a2, a3;
                ldm_x4(a0, a1, a2, a3, baseW2 + (2 * p) * 2176 + kk2 * 64);
                mma16816(xA, af[2 * kk2],     a0, a1);
                mma16816(xA, af[2 * kk2 + 1], a2, a3);
                ldm_x4(a0, a1, a2, a3, baseW2 + (2 * p + 1) * 2176 + kk2 * 64);
                mma16816(xB, af[2 * kk2],     a0, a1);
                mma16816(xB, af[2 * kk2 + 1], a2, a3);
            }
            const int c = p * 16 + t4 * 2;
            float b20 = sm->b2s[c],     b21 = sm->b2s[c + 1];
            float b28 = sm->b2s[c + 8], b29 = sm->b2s[c + 9];
            af2[p][0] = pack2(fmaxf(xA[0] + b20, 0.f), fmaxf(xA[1] + b21, 0.f));
            af2[p][1] = pack2(fmaxf(xA[2] + b20, 0.f), fmaxf(xA[3] + b21, 0.f));
            af2[p][2] = pack2(fmaxf(xB[0] + b28, 0.f), fmaxf(xB[1] + b29, 0.f));
            af2[p][3] = pack2(fmaxf(xB[2] + b28, 0.f), fmaxf(xB[3] + b29, 0.f));
        }

        // ---- att layer-1 fragments ----
        #pragma unroll
        for (int kk = 0; kk < 4; kk++) {
            const int c = kk * 16 + t4 * 2;
            unsigned w01 = *reinterpret_cast<const unsigned*>(&sm->aw1Lh[c]);
            unsigned w89 = *reinterpret_cast<const unsigned*>(&sm->aw1Lh[c + 8]);
            unsigned q01 = *reinterpret_cast<const unsigned*>(&Q1i[c]);
            unsigned q89 = *reinterpret_cast<const unsigned*>(&Q1i[c + 8]);
            unsigned f0, f1, f2, f3;
            ldm_x4(f0, f1, f2, f3, addrQ2 + kk * 32);
            afQ[kk][0] = frag_fix(f0, dA2, w01, q01, z2);
            afQ[kk][1] = frag_fix(f1, dB2, w01, q01, z2);
            afQ[kk][2] = frag_fix(f2, dA2, w89, q89, z2);
            afQ[kk][3] = frag_fix(f3, dB2, w89, q89, z2);
        }

        // ---- fused GEMM2 + att GEMM + sigmoid + combine ----
        #pragma unroll
        for (int nt = 0; nt < 16; nt++) {
            float dr[4] = {0.f, 0.f, 0.f, 0.f};
            float da[4] = {0.f, 0.f, 0.f, 0.f};
            #pragma unroll
            for (int kk2 = 0; kk2 < 4; kk2++) {
                unsigned r0, r1, r2, r3;
                ldm_x4(r0, r1, r2, r3, baseW3 + nt * 2176 + kk2 * 64);
                mma16816(dr, af2[2 * kk2],     r0, r1);
                mma16816(dr, af2[2 * kk2 + 1], r2, r3);
            }
            #pragma unroll
            for (int kk2 = 0; kk2 < 2; kk2++) {
                unsigned r0, r1, r2, r3;
                ldm_x4(r0, r1, r2, r3, baseAW + nt * 1152 + kk2 * 64);
                mma16816(da, afQ[2 * kk2],     r0, r1);
                mma16816(da, afQ[2 * kk2 + 1], r2, r3);
            }
            const int c0 = nt * 8 + t4 * 2;
            float b30 = sm->b3s[c0], b31 = sm->b3s[c0 + 1];
            float ab0 = sm->ab2s[c0], ab1 = sm->ab2s[c0 + 1];
            // sigmoid(x) = 0.5*tanh(0.5x) + 0.5
            float s0 = fmaf(0.5f, tanhfast(0.5f * (da[0] + ab0)), 0.5f);
            float s1 = fmaf(0.5f, tanhfast(0.5f * (da[1] + ab1)), 0.5f);
            float s2 = fmaf(0.5f, tanhfast(0.5f * (da[2] + ab0)), 0.5f);
            float s3 = fmaf(0.5f, tanhfast(0.5f * (da[3] + ab1)), 0.5f);
            float r0 = fmaxf(dr[0] + b30, 0.f);
            float r1 = fmaxf(dr[1] + b31, 0.f);
            float r2 = fmaxf(dr[2] + b30, 0.f);
            float r3 = fmaxf(dr[3] + b31, 0.f);
            vacc0[nt] += r0 * s0 + r2 * s2;
            vacc1[nt] += r1 * s1 + r3 * s3;
        }
    }

    // ---- one reduction per warp ----
    #pragma unroll
    for (int nt = 0; nt < 16; nt++) {
        float v0 = vacc0[nt], v1 = vacc1[nt];
        v0 += __shfl_xor_sync(0xffffffffu, v0, 4);
        v0 += __shfl_xor_sync(0xffffffffu, v0, 8);
        v0 += __shfl_xor_sync(0xffffffffu, v0, 16);
        v1 += __shfl_xor_sync(0xffffffffu, v1, 4);
        v1 += __shfl_xor_sync(0xffffffffu, v1, 8);
        v1 += __shfl_xor_sync(0xffffffffu, v1, 16);
        if (lane < 4) {
            atomicAdd(&sm->accs[nt * 8 + lane * 2], v0);
            atomicAdd(&sm->accs[nt * 8 + lane * 2 + 1], v1);
        }
    }
    __syncthreads();

    // ---------------- Epilogue: self_dyn + final mean ----------------
    float* SW1 = reinterpret_cast<float*>(sm->W2T);  // reuse 32 KB
    for (int idx = tid; idx < 8192; idx += NTHREADS) SW1[idx] = sd_w1[idx];
    __syncthreads();
    if (tid < 256) {
        int c = tid & 127, hh = tid >> 7;
        float a = 0.f;
        for (int i = hh * 32; i < hh * 32 + 32; i++) {
            const float* hr = sm->H[i];
            float u = sd_b1[c];
            #pragma unroll 8
            for (int k = 0; k < 64; k++) u += hr[k] * SW1[k * 128 + c];
            a += fmaxf(u, 0.f);
        }
        atomicAdd(&sm->msum[c], a);
    }
    __syncthreads();
    if (tid < 128) {
        // contraction over 2cl = 128 dims (sd_w2 is 128x128)
        float r = sd_b2[tid] + sm->accs[tid] * (1.f / 4096.f);
        #pragma unroll 8
        for (int k = 0; k < 128; k++)
            r += (sm->msum[k] * (1.f / 64.f)) * sd_w2[k * 128 + tid];
        out[(size_t)b * 128 + tid] = r;
    }
}

extern "C" void kernel_launch(void* const* d_in, const int* in_sizes, int n_in,
                              void* d_out, int out_size) {
    (void)in_sizes; (void)n_in; (void)out_size;
    cudaFuncSetAttribute(sgh_kernel, cudaFuncAttributeMaxDynamicSharedMemorySize,
                         (int)sizeof(Smem));
    const float* s     = (const float*)d_in[0];
    const float* se_w1 = (const float*)d_in[1];
    const float* se_b1 = (const float*)d_in[2];
    const float* se_w2 = (const float*)d_in[3];
    const float* se_b2 = (const float*)d_in[4];
    const float* sd_w1 = (const float*)d_in[5];
    const float* sd_b1 = (const float*)d_in[6];
    const float* sd_w2 = (const float*)d_in[7];
    const float* sd_b2 = (const float*)d_in[8];
    const float* rc_w1 = (const float*)d_in[9];
    const float* rc_b1 = (const float*)d_in[10];
    const float* rc_w2 = (const float*)d_in[11];
    const float* rc_b2 = (const float*)d_in[12];
    const float* rc_w3 = (const float*)d_in[13];
    const float* rc_b3 = (const float*)d_in[14];
    const float* an_w1 = (const float*)d_in[15];
    const float* an_b1 = (const float*)d_in[16];
    const float* an_w2 = (const float*)d_in[17];
    const float* an_b2 = (const float*)d_in[18];

    sgh_kernel<<<128, NTHREADS, sizeof(Smem)>>>(
        s, se_w1, se_b1, se_w2, se_b2, sd_w1, sd_b1, sd_w2, sd_b2,
        rc_w1, rc_b1, rc_w2, rc_b2, rc_w3, rc_b3,
        an_w1, an_b1, an_w2, an_b2, (float*)d_out);
}